// round 3
// baseline (speedup 1.0000x reference)
#include <cuda_runtime.h>
#include <math.h>

// ---------------- dims ----------------
static const int cB  = 8;
static const int cL  = 1152;      // T*W
static const int cD  = 512;
static const int cH  = 8;
static const int cE  = 64;
static const int cDI = 1024;
static const int cS  = 64;
static const int cR  = 32;
static const int cDFF= 2048;
static const int cM  = 9216;      // B*L

// ---------------- workspaces (device globals; no allocations) ----------------
__device__ float g_q   [cM*cD];
__device__ float g_kk  [cM*cD];
__device__ float g_vv  [cM*cD];
__device__ float g_ao  [cM*cD];
__device__ float g_attn[cM*cD];
__device__ float g_xz  [cM*2*cDI];
__device__ float g_u   [cM*cDI];
__device__ float g_xdbc[cM*160];
__device__ float g_dlt [cM*cDI];
__device__ float g_y   [cM*cDI];
__device__ float g_mmb [cM*cD];
__device__ float g_h   [cM*cD];
__device__ float g_hn  [cM*cD];
__device__ float g_ff1 [cM*cDFF];

// ---------------- f32x2 helpers ----------------
__device__ __forceinline__ unsigned long long dupf(float a){
    unsigned long long r;
    asm("mov.b64 %0, {%1,%1};" : "=l"(r) : "f"(a));
    return r;
}
__device__ __forceinline__ void fma2(unsigned long long &d, unsigned long long a, unsigned long long b){
    asm("fma.rn.f32x2 %0, %1, %2, %0;" : "+l"(d) : "l"(a), "l"(b));
}
union F4U { float4 f4; unsigned long long l[2]; float f[4]; };

// ---------------- epilogue math ----------------
__device__ __forceinline__ float softplus_f(float v){
    return fmaxf(v, 0.0f) + log1pf(__expf(-fabsf(v)));
}
__device__ __forceinline__ float gelu_f(float v){
    return 0.5f * v * (1.0f + erff(v * 0.70710678118654752f));
}

// =====================================================================
// SGEMM: C[m][n] = sum_k A[m][k] * W[n][k]  (+ epilogue)
// A: [M x K] row stride lda; W: [N x K] dense; C: [M x N] dense.
// M is always a multiple of 128, K a multiple of 16. N guarded.
// EPI: 0=none 1=bias 2=bias+softplus 3=bias+gelu 4=bias+residual
// =====================================================================
template<int EPI>
__global__ __launch_bounds__(256, 2) void sgemm_nt(
    const float* __restrict__ A, int lda,
    const float* __restrict__ Wt,
    const float* __restrict__ bias,
    const float* __restrict__ res,
    float* __restrict__ C,
    int N, int K)
{
    __shared__ float As[16][132];
    __shared__ float Ws[16][132];
    const int tid = threadIdx.x;
    const int bm = blockIdx.y * 128, bn = blockIdx.x * 128;
    const int tx = tid & 15, ty = tid >> 4;
    const int arow = tid >> 2;
    const int acol = (tid & 3) * 4;

    unsigned long long acc[4][8];
#pragma unroll
    for (int i = 0; i < 4; i++)
#pragma unroll
        for (int j = 0; j < 8; j++) acc[i][j] = 0ULL;

    for (int k0 = 0; k0 < K; k0 += 16){
        F4U a0, a1, w0, w1;
        a0.f4 = *(const float4*)&A[(size_t)(bm + arow     ) * lda + k0 + acol];
        a1.f4 = *(const float4*)&A[(size_t)(bm + arow + 64) * lda + k0 + acol];
        const int wr0 = bn + arow, wr1 = bn + arow + 64;
        if (wr0 < N) w0.f4 = *(const float4*)&Wt[(size_t)wr0 * K + k0 + acol];
        else         w0.f4 = make_float4(0.f,0.f,0.f,0.f);
        if (wr1 < N) w1.f4 = *(const float4*)&Wt[(size_t)wr1 * K + k0 + acol];
        else         w1.f4 = make_float4(0.f,0.f,0.f,0.f);

        __syncthreads();
#pragma unroll
        for (int c = 0; c < 4; c++){
            As[acol + c][arow     ] = a0.f[c];
            As[acol + c][arow + 64] = a1.f[c];
            Ws[acol + c][arow     ] = w0.f[c];
            Ws[acol + c][arow + 64] = w1.f[c];
        }
        __syncthreads();

#pragma unroll
        for (int kkk = 0; kkk < 16; kkk++){
            F4U av0, av1, wv0, wv1;
            av0.f4 = *(const float4*)&As[kkk][ty * 8];
            av1.f4 = *(const float4*)&As[kkk][ty * 8 + 4];
            wv0.f4 = *(const float4*)&Ws[kkk][tx * 8];
            wv1.f4 = *(const float4*)&Ws[kkk][tx * 8 + 4];
            unsigned long long wd[8];
#pragma unroll
            for (int j = 0; j < 4; j++){ wd[j] = dupf(wv0.f[j]); wd[4 + j] = dupf(wv1.f[j]); }
#pragma unroll
            for (int j = 0; j < 8; j++){
                fma2(acc[0][j], av0.l[0], wd[j]);
                fma2(acc[1][j], av0.l[1], wd[j]);
                fma2(acc[2][j], av1.l[0], wd[j]);
                fma2(acc[3][j], av1.l[1], wd[j]);
            }
        }
    }

    // epilogue: acc[ip][j] holds rows (ty*8+2*ip, +1), col tx*8+j
#pragma unroll
    for (int ip = 0; ip < 4; ip++){
#pragma unroll
        for (int j = 0; j < 8; j++){
            const int n = bn + tx * 8 + j;
            if (n >= N) continue;
            const unsigned long long t = acc[ip][j];
            float r0 = __uint_as_float((unsigned)(t & 0xffffffffULL));
            float r1 = __uint_as_float((unsigned)(t >> 32));
            const int m0 = bm + ty * 8 + 2 * ip;
            if (EPI >= 1){ const float bb = bias[n]; r0 += bb; r1 += bb; }
            if (EPI == 2){ r0 = softplus_f(r0); r1 = softplus_f(r1); }
            if (EPI == 3){ r0 = gelu_f(r0);     r1 = gelu_f(r1); }
            if (EPI == 4){
                r0 += res[(size_t)m0 * N + n];
                r1 += res[(size_t)(m0 + 1) * N + n];
            }
            C[(size_t)m0 * N + n]       = r0;
            C[(size_t)(m0 + 1) * N + n] = r1;
        }
    }
}

// =====================================================================
// Flash attention: per (b,h), 64 q-rows per block, streaming over K/V.
// Layout: Q/K/V are [M, 512] with head h in cols h*64 .. h*64+63.
// =====================================================================
__global__ __launch_bounds__(256) void flash_attn(
    const float* __restrict__ Q, const float* __restrict__ K, const float* __restrict__ V,
    const unsigned char* __restrict__ mask, float* __restrict__ O)
{
    extern __shared__ float smx[];
    float* Qs = smx;                 // 64*68
    float* Ks = Qs + 64 * 68;
    float* Vs = Ks + 64 * 68;
    float* Ps = Vs + 64 * 68;
    float* msk = Ps + 64 * 68;       // 64

    const int tid = threadIdx.x, tx = tid & 15, ty = tid >> 4;
    const int bh = blockIdx.y;
    const int b = bh >> 3, h = bh & 7;
    const int q0 = blockIdx.x * 64;
    const size_t basebl = (size_t)b * cL;

    for (int i = tid; i < 1024; i += 256){
        const int r = i >> 4, c = (i & 15) * 4;
        *(float4*)&Qs[r * 68 + c] = *(const float4*)&Q[(basebl + q0 + r) * cD + h * 64 + c];
    }

    float o[4][4], mrow[4], lrow[4];
#pragma unroll
    for (int i = 0; i < 4; i++){
        mrow[i] = -1e30f; lrow[i] = 0.f;
#pragma unroll
        for (int j = 0; j < 4; j++) o[i][j] = 0.f;
    }

    for (int jt = 0; jt < cL / 64; jt++){
        __syncthreads();
        const int k0 = jt * 64;
        for (int i = tid; i < 1024; i += 256){
            const int r = i >> 4, c = (i & 15) * 4;
            *(float4*)&Ks[r * 68 + c] = *(const float4*)&K[(basebl + k0 + r) * cD + h * 64 + c];
            *(float4*)&Vs[r * 68 + c] = *(const float4*)&V[(basebl + k0 + r) * cD + h * 64 + c];
        }
        if (tid < 64) msk[tid] = mask[b * cL + k0 + tid] ? -1e30f : 0.0f;
        __syncthreads();

        float s[4][4];
#pragma unroll
        for (int i = 0; i < 4; i++)
#pragma unroll
            for (int j = 0; j < 4; j++) s[i][j] = 0.f;

#pragma unroll 4
        for (int k = 0; k < 64; k += 4){
            F4U qv[4], kv[4];
#pragma unroll
            for (int i = 0; i < 4; i++) qv[i].f4 = *(const float4*)&Qs[(ty * 4 + i) * 68 + k];
#pragma unroll
            for (int j = 0; j < 4; j++) kv[j].f4 = *(const float4*)&Ks[(tx * 4 + j) * 68 + k];
#pragma unroll
            for (int i = 0; i < 4; i++)
#pragma unroll
                for (int j = 0; j < 4; j++)
                    s[i][j] += qv[i].f[0]*kv[j].f[0] + qv[i].f[1]*kv[j].f[1]
                             + qv[i].f[2]*kv[j].f[2] + qv[i].f[3]*kv[j].f[3];
        }

#pragma unroll
        for (int i = 0; i < 4; i++){
            float sv[4];
#pragma unroll
            for (int j = 0; j < 4; j++) sv[j] = s[i][j] * 0.125f + msk[tx * 4 + j];
            float rm = fmaxf(fmaxf(sv[0], sv[1]), fmaxf(sv[2], sv[3]));
#pragma unroll
            for (int off = 1; off < 16; off <<= 1)
                rm = fmaxf(rm, __shfl_xor_sync(0xffffffffu, rm, off));
            const float mnew = fmaxf(mrow[i], rm);
            const float fac = __expf(mrow[i] - mnew);
            float rs = 0.f;
#pragma unroll
            for (int j = 0; j < 4; j++){
                const float p = __expf(sv[j] - mnew);
                rs += p;
                Ps[(ty * 4 + i) * 68 + tx * 4 + j] = p;
            }
#pragma unroll
            for (int off = 1; off < 16; off <<= 1)
                rs += __shfl_xor_sync(0xffffffffu, rs, off);
            lrow[i] = lrow[i] * fac + rs;
            mrow[i] = mnew;
#pragma unroll
            for (int j = 0; j < 4; j++) o[i][j] *= fac;
        }
        __syncthreads();

#pragma unroll 4
        for (int n = 0; n < 64; n += 4){
            F4U pv[4], vr[4];
#pragma unroll
            for (int i = 0; i < 4; i++) pv[i].f4 = *(const float4*)&Ps[(ty * 4 + i) * 68 + n];
#pragma unroll
            for (int jj = 0; jj < 4; jj++) vr[jj].f4 = *(const float4*)&Vs[(n + jj) * 68 + tx * 4];
#pragma unroll
            for (int i = 0; i < 4; i++)
#pragma unroll
                for (int e = 0; e < 4; e++)
                    o[i][e] += pv[i].f[0]*vr[0].f[e] + pv[i].f[1]*vr[1].f[e]
                             + pv[i].f[2]*vr[2].f[e] + pv[i].f[3]*vr[3].f[e];
        }
    }

#pragma unroll
    for (int i = 0; i < 4; i++){
        const float inv = 1.0f / lrow[i];
#pragma unroll
        for (int e = 0; e < 4; e++)
            O[(basebl + q0 + ty * 4 + i) * cD + h * 64 + tx * 4 + e] = o[i][e] * inv;
    }
}

// =====================================================================
// Depthwise causal conv (KC=4) + SiLU.  in: g_xz[:, :DI] ; out: g_u
// =====================================================================
__global__ __launch_bounds__(256) void conv_silu(
    const float* __restrict__ xz, const float* __restrict__ cw,
    const float* __restrict__ cb, float* __restrict__ u)
{
    const long idx = (long)blockIdx.x * 256 + threadIdx.x;  // over M*DI
    const int c = (int)(idx & (cDI - 1));
    const int m = (int)(idx >> 10);
    const int b = m / cL, l = m % cL;
    float acc = cb[c];
#pragma unroll
    for (int k = 0; k < 4; k++){
        const int ls = l + k - 3;
        if (ls >= 0)
            acc += xz[((size_t)(b * cL + ls)) * (2 * cDI) + c] * cw[c * 4 + k];
    }
    acc = acc / (1.0f + __expf(-acc));   // silu
    u[(size_t)m * cDI + c] = acc;
}

// =====================================================================
// Selective scan: warp per (b, d). 2 states per lane (S=64).
// h_t = h_{t-1}*exp(dt*A) + dt*u*B_t ;  y = <h, C_t> + u*D ;  y *= silu(z)
// =====================================================================
__global__ __launch_bounds__(256) void mamba_scan(
    const float* __restrict__ delta, const float* __restrict__ u,
    const float* __restrict__ xdbc, const float* __restrict__ xz,
    const float* __restrict__ A_log, const float* __restrict__ Dssm,
    float* __restrict__ y)
{
    const int warp = threadIdx.x >> 5, lane = threadIdx.x & 31;
    const int d = blockIdx.x * 8 + warp;
    const int b = blockIdx.y;
    const float a0 = -__expf(A_log[d * cS + 2 * lane]);
    const float a1 = -__expf(A_log[d * cS + 2 * lane + 1]);
    const float Dd = Dssm[d];
    float h0 = 0.f, h1 = 0.f;
    const size_t base = (size_t)b * cL;

    for (int t = 0; t < cL; t++){
        const size_t m = base + t;
        const float dt = __ldg(&delta[m * cDI + d]);
        const float uu = __ldg(&u[m * cDI + d]);
        const float2 Bv = *(const float2*)&xdbc[m * 160 + 32 + 2 * lane];
        const float2 Cv = *(const float2*)&xdbc[m * 160 + 96 + 2 * lane];
        const float du = dt * uu;
        h0 = h0 * __expf(dt * a0) + du * Bv.x;
        h1 = h1 * __expf(dt * a1) + du * Bv.y;
        float p = h0 * Cv.x + h1 * Cv.y;
        p += __shfl_xor_sync(0xffffffffu, p, 16);
        p += __shfl_xor_sync(0xffffffffu, p, 8);
        p += __shfl_xor_sync(0xffffffffu, p, 4);
        p += __shfl_xor_sync(0xffffffffu, p, 2);
        p += __shfl_xor_sync(0xffffffffu, p, 1);
        if (lane == 0){
            const float z = xz[m * (2 * cDI) + cDI + d];
            float yv = p + uu * Dd;
            yv *= z / (1.0f + __expf(-z));
            y[m * cDI + d] = yv;
        }
    }
}

// =====================================================================
// Fused residual-sum + LN1 + LN2.  h = LN1(xf+attn+mamba); hn = LN2(h)
// =====================================================================
__device__ __forceinline__ float blockSum256(float v, float* red){
#pragma unroll
    for (int off = 16; off > 0; off >>= 1) v += __shfl_xor_sync(0xffffffffu, v, off);
    if ((threadIdx.x & 31) == 0) red[threadIdx.x >> 5] = v;
    __syncthreads();
    const float s = red[0]+red[1]+red[2]+red[3]+red[4]+red[5]+red[6]+red[7];
    __syncthreads();
    return s;
}

__global__ __launch_bounds__(256) void ln_fuse(
    const float* __restrict__ xf, const float* __restrict__ attn, const float* __restrict__ mamba,
    const float* __restrict__ g1, const float* __restrict__ b1,
    const float* __restrict__ g2, const float* __restrict__ b2,
    float* __restrict__ h, float* __restrict__ hn)
{
    __shared__ float red[8];
    const size_t m = blockIdx.x;
    const int t = threadIdx.x;
    const size_t r = m * cD;
    float v0 = xf[r + t]       + attn[r + t]       + mamba[r + t];
    float v1 = xf[r + 256 + t] + attn[r + 256 + t] + mamba[r + 256 + t];

    const float mean = blockSum256(v0 + v1, red) * (1.0f / cD);
    const float d0 = v0 - mean, d1 = v1 - mean;
    const float var = blockSum256(d0 * d0 + d1 * d1, red) * (1.0f / cD);
    const float inv = rsqrtf(var + 1e-5f);
    const float h0 = d0 * inv * g1[t]       + b1[t];
    const float h1 = d1 * inv * g1[256 + t] + b1[256 + t];
    h[r + t] = h0;
    h[r + 256 + t] = h1;

    const float mean2 = blockSum256(h0 + h1, red) * (1.0f / cD);
    const float e0 = h0 - mean2, e1 = h1 - mean2;
    const float var2 = blockSum256(e0 * e0 + e1 * e1, red) * (1.0f / cD);
    const float inv2 = rsqrtf(var2 + 1e-6f);
    hn[r + t]       = e0 * inv2 * g2[t]       + b2[t];
    hn[r + 256 + t] = e1 * inv2 * g2[256 + t] + b2[256 + t];
}

// =====================================================================
// Launch
// =====================================================================
extern "C" void kernel_launch(void* const* d_in, const int* in_sizes, int n_in,
                              void* d_out, int out_size)
{
    (void)in_sizes; (void)n_in; (void)out_size;
    const float* x      = (const float*)d_in[0];
    const unsigned char* mask = (const unsigned char*)d_in[1];
    const float* Wq = (const float*)d_in[2];  const float* bq = (const float*)d_in[3];
    const float* Wk = (const float*)d_in[4];  const float* bk = (const float*)d_in[5];
    const float* Wv = (const float*)d_in[6];  const float* bv = (const float*)d_in[7];
    const float* Wo = (const float*)d_in[8];  const float* bo = (const float*)d_in[9];
    const float* in_w   = (const float*)d_in[10];
    const float* conv_w = (const float*)d_in[11];
    const float* conv_b = (const float*)d_in[12];
    const float* xproj_w= (const float*)d_in[13];
    const float* dt_w   = (const float*)d_in[14];
    const float* dt_b   = (const float*)d_in[15];
    const float* A_log  = (const float*)d_in[16];
    const float* Dssm   = (const float*)d_in[17];
    const float* outp_w = (const float*)d_in[18];
    const float* ln1g   = (const float*)d_in[19];
    const float* ln1b   = (const float*)d_in[20];
    const float* fw1    = (const float*)d_in[21];
    const float* fb1    = (const float*)d_in[22];
    const float* fw2    = (const float*)d_in[23];
    const float* fb2    = (const float*)d_in[24];
    const float* ln2g   = (const float*)d_in[25];
    const float* ln2b   = (const float*)d_in[26];
    float* out = (float*)d_out;

    float *q,*k,*v,*ao,*attn,*xz,*u,*xdbc,*dlt,*y,*mmb,*h,*hn,*ff1;
    cudaGetSymbolAddress((void**)&q,    g_q);
    cudaGetSymbolAddress((void**)&k,    g_kk);
    cudaGetSymbolAddress((void**)&v,    g_vv);
    cudaGetSymbolAddress((void**)&ao,   g_ao);
    cudaGetSymbolAddress((void**)&attn, g_attn);
    cudaGetSymbolAddress((void**)&xz,   g_xz);
    cudaGetSymbolAddress((void**)&u,    g_u);
    cudaGetSymbolAddress((void**)&xdbc, g_xdbc);
    cudaGetSymbolAddress((void**)&dlt,  g_dlt);
    cudaGetSymbolAddress((void**)&y,    g_y);
    cudaGetSymbolAddress((void**)&mmb,  g_mmb);
    cudaGetSymbolAddress((void**)&h,    g_h);
    cudaGetSymbolAddress((void**)&hn,   g_hn);
    cudaGetSymbolAddress((void**)&ff1,  g_ff1);

    const int flashSmem = (4 * 64 * 68 + 64) * 4;
    cudaFuncSetAttribute(flash_attn, cudaFuncAttributeMaxDynamicSharedMemorySize, flashSmem);

    // ---- attention branch ----
    sgemm_nt<1><<<dim3(4, 72), 256>>>(x, cD, Wq, bq, nullptr, q, cD, cD);
    sgemm_nt<1><<<dim3(4, 72), 256>>>(x, cD, Wk, bk, nullptr, k, cD, cD);
    sgemm_nt<1><<<dim3(4, 72), 256>>>(x, cD, Wv, bv, nullptr, v, cD, cD);
    flash_attn<<<dim3(cL / 64, cB * cH), 256, flashSmem>>>(q, k, v, mask, ao);
    sgemm_nt<1><<<dim3(4, 72), 256>>>(ao, cD, Wo, bo, nullptr, attn, cD, cD);

    // ---- mamba branch ----
    sgemm_nt<0><<<dim3(16, 72), 256>>>(x, cD, in_w, nullptr, nullptr, xz, 2 * cDI, cD);
    conv_silu<<<(cM * cDI) / 256, 256>>>(xz, conv_w, conv_b, u);
    sgemm_nt<0><<<dim3(2, 72), 256>>>(u, cDI, xproj_w, nullptr, nullptr, xdbc, 160, cDI);
    sgemm_nt<2><<<dim3(8, 72), 256>>>(xdbc, 160, dt_w, dt_b, nullptr, dlt, cDI, cR);
    mamba_scan<<<dim3(cDI / 8, cB), 256>>>(dlt, u, xdbc, xz, A_log, Dssm, y);
    sgemm_nt<0><<<dim3(4, 72), 256>>>(y, cDI, outp_w, nullptr, nullptr, mmb, cD, cDI);

    // ---- merge + LN + FFN ----
    ln_fuse<<<cM, 256>>>(x, attn, mmb, ln1g, ln1b, ln2g, ln2b, h, hn);
    sgemm_nt<3><<<dim3(16, 72), 256>>>(hn, cD, fw1, fb1, nullptr, ff1, cDFF, cD);
    sgemm_nt<4><<<dim3(4, 72), 256>>>(ff1, cDFF, fw2, fb2, h, out, cD, cDFF);
}